// round 3
// baseline (speedup 1.0000x reference)
#include <cuda_runtime.h>
#include <math.h>

// Problem constants (fixed shapes: B=16, W=4096)
#define NTOK   65536          // B*W
#define DM     128            // d_model
#define HIDN   256            // hidden
#define NN     17             // nodes
#define NF     32             // node feature dim
#define NODE_TOT 544          // 17*32
#define OUTW   34             // 17*2

// Scratch (allocation-free: __device__ globals)
__device__ float g_h[(size_t)NTOK * HIDN];        // 64 MB
__device__ float g_nodes[(size_t)NTOK * NODE_TOT]; // 136 MB

__device__ __forceinline__ float gelu_erf(float v) {
    return 0.5f * v * (1.0f + erff(v * 0.7071067811865476f));
}

// ---------------------------------------------------------------------------
// Generic tiled SGEMM:  C[M,N] = act(A[M,K] @ B[K,N] + bias[N])
// BM=64, BN=64, BK=16, TM=TN=4, 256 threads. M % 64 == 0, K % 16 == 0, N % 4 == 0.
// ---------------------------------------------------------------------------
template <bool GELU>
__global__ __launch_bounds__(256) void gemm_bias_kernel(
    const float* __restrict__ A, const float* __restrict__ B,
    const float* __restrict__ bias, float* __restrict__ C,
    int M, int N, int K)
{
    __shared__ __align__(16) float As[16][64];   // [k][m] transposed A tile
    __shared__ __align__(16) float Bs[16][64];   // [k][n]

    const int tid = threadIdx.x;
    const int bm = blockIdx.y * 64;
    const int bn = blockIdx.x * 64;

    const int tr = tid >> 4;          // 0..15  -> C row group (4 rows)
    const int tc = tid & 15;          // 0..15  -> C col group (4 cols)

    // A tile load mapping: one float4 per thread
    const int ar  = tid >> 2;         // 0..63 row within tile
    const int ak4 = tid & 3;          // 0..3  k-group (4 floats)
    // B tile load mapping: one float4 per thread
    const int br  = tid >> 4;         // 0..15 k row
    const int bc4 = tid & 15;         // 0..15 col group

    float acc[4][4];
#pragma unroll
    for (int m = 0; m < 4; m++)
#pragma unroll
        for (int n = 0; n < 4; n++) acc[m][n] = 0.0f;

    for (int k0 = 0; k0 < K; k0 += 16) {
        // Load A tile (rows always valid; K multiple of 16)
        {
            const float4 av = *reinterpret_cast<const float4*>(
                A + (size_t)(bm + ar) * K + k0 + ak4 * 4);
            As[ak4 * 4 + 0][ar] = av.x;
            As[ak4 * 4 + 1][ar] = av.y;
            As[ak4 * 4 + 2][ar] = av.z;
            As[ak4 * 4 + 3][ar] = av.w;
        }
        // Load B tile (guard N edge; N multiple of 4 so float4 fully in or out)
        {
            const int col = bn + bc4 * 4;
            float4 bv = make_float4(0.f, 0.f, 0.f, 0.f);
            if (col < N)
                bv = *reinterpret_cast<const float4*>(
                    B + (size_t)(k0 + br) * N + col);
            *reinterpret_cast<float4*>(&Bs[br][bc4 * 4]) = bv;
        }
        __syncthreads();

#pragma unroll
        for (int kk = 0; kk < 16; kk++) {
            const float4 av = *reinterpret_cast<const float4*>(&As[kk][tr * 4]);
            const float4 bv = *reinterpret_cast<const float4*>(&Bs[kk][tc * 4]);
            const float a4[4] = {av.x, av.y, av.z, av.w};
            const float b4[4] = {bv.x, bv.y, bv.z, bv.w};
#pragma unroll
            for (int m = 0; m < 4; m++)
#pragma unroll
                for (int n = 0; n < 4; n++)
                    acc[m][n] = fmaf(a4[m], b4[n], acc[m][n]);
        }
        __syncthreads();
    }

    const int row0 = bm + tr * 4;
#pragma unroll
    for (int m = 0; m < 4; m++) {
        const int row = row0 + m;
#pragma unroll
        for (int n = 0; n < 4; n++) {
            const int col = bn + tc * 4 + n;
            if (col < N) {
                float v = acc[m][n] + bias[col];
                if (GELU) v = gelu_erf(v);
                C[(size_t)row * N + col] = v;
            }
        }
    }
}

// ---------------------------------------------------------------------------
// Fused GAT1 + GAT2 + coord projection. One warp per token.
// Lane l owns feature l of every node. Adjacency (softmaxed) in SMEM
// (broadcast reads). Wg columns register-resident; 32->32 linear via shfl.
// ---------------------------------------------------------------------------
__global__ __launch_bounds__(256) void gat_kernel(
    const float* __restrict__ nodes,
    const float* __restrict__ adj1, const float* __restrict__ Wg1, const float* __restrict__ bg1,
    const float* __restrict__ adj2, const float* __restrict__ Wg2, const float* __restrict__ bg2,
    const float* __restrict__ Wc,  const float* __restrict__ bc,
    float* __restrict__ out, int ntok)
{
    __shared__ float a1s[NN][NN];
    __shared__ float a2s[NN][NN];

    const int tid = threadIdx.x;

    // Row softmax of both adjacency matrices (34 threads do the tiny work)
    if (tid < 2 * NN) {
        const bool first = (tid < NN);
        const float* src = first ? adj1 : adj2;
        const int row = first ? tid : tid - NN;
        float v[NN];
        float mx = -1e30f;
#pragma unroll
        for (int j = 0; j < NN; j++) { v[j] = src[row * NN + j]; mx = fmaxf(mx, v[j]); }
        float s = 0.0f;
#pragma unroll
        for (int j = 0; j < NN; j++) { v[j] = expf(v[j] - mx); s += v[j]; }
        const float inv = 1.0f / s;
        float* dst = first ? &a1s[row][0] : &a2s[row][0];
#pragma unroll
        for (int j = 0; j < NN; j++) dst[j] = v[j] * inv;
    }
    __syncthreads();

    const int lane = tid & 31;
    const int warp = tid >> 5;

    // Per-lane register weights: column `lane` of Wg1/Wg2, row `lane` of Wc
    float wg1[NF], wg2[NF];
#pragma unroll
    for (int g = 0; g < NF; g++) {
        wg1[g] = Wg1[g * NF + lane];
        wg2[g] = Wg2[g * NF + lane];
    }
    const float bg1v = bg1[lane];
    const float bg2v = bg2[lane];
    const float wc0 = Wc[lane * 2 + 0];
    const float wc1 = Wc[lane * 2 + 1];
    const float bc0 = bc[0], bc1 = bc[1];

    const int gw = blockIdx.x * (blockDim.x >> 5) + warp;
    const int nwarps = gridDim.x * (blockDim.x >> 5);

    for (int t = gw; t < ntok; t += nwarps) {
        const float* np = nodes + (size_t)t * NODE_TOT;
        float n[NN];
#pragma unroll
        for (int j = 0; j < NN; j++) n[j] = np[j * NF + lane];

        // ---- GAT layer 1 ----
        float mx1[NN];
#pragma unroll
        for (int i = 0; i < NN; i++) {
            float m = 0.0f;
#pragma unroll
            for (int j = 0; j < NN; j++) m = fmaf(a1s[i][j], n[j], m);
            mx1[i] = m;
        }
#pragma unroll
        for (int i = 0; i < NN; i++) {
            float acc = bg1v;
#pragma unroll
            for (int g = 0; g < NF; g++)
                acc = fmaf(__shfl_sync(0xffffffffu, mx1[i], g), wg1[g], acc);
            n[i] = gelu_erf(acc) + n[i];
        }

        // ---- GAT layer 2 ----
        float mx2[NN];
#pragma unroll
        for (int i = 0; i < NN; i++) {
            float m = 0.0f;
#pragma unroll
            for (int j = 0; j < NN; j++) m = fmaf(a2s[i][j], n[j], m);
            mx2[i] = m;
        }
#pragma unroll
        for (int i = 0; i < NN; i++) {
            float acc = bg2v;
#pragma unroll
            for (int g = 0; g < NF; g++)
                acc = fmaf(__shfl_sync(0xffffffffu, mx2[i], g), wg2[g], acc);
            n[i] = gelu_erf(acc) + n[i];
        }

        // ---- coord projection: [17,32] @ [32,2] + bc ----
#pragma unroll
        for (int i = 0; i < NN; i++) {
            float v0 = n[i] * wc0;
            float v1 = n[i] * wc1;
#pragma unroll
            for (int off = 16; off > 0; off >>= 1) {
                v0 += __shfl_xor_sync(0xffffffffu, v0, off);
                v1 += __shfl_xor_sync(0xffffffffu, v1, off);
            }
            if (lane == 0) {
                out[(size_t)t * OUTW + i * 2 + 0] = v0 + bc0;
                out[(size_t)t * OUTW + i * 2 + 1] = v1 + bc1;
            }
        }
    }
}

// ---------------------------------------------------------------------------
extern "C" void kernel_launch(void* const* d_in, const int* in_sizes, int n_in,
                              void* d_out, int out_size)
{
    const float* x    = (const float*)d_in[0];
    const float* W1   = (const float*)d_in[1];
    const float* b1   = (const float*)d_in[2];
    const float* W2   = (const float*)d_in[3];
    const float* b2   = (const float*)d_in[4];
    const float* adj1 = (const float*)d_in[5];
    const float* Wg1  = (const float*)d_in[6];
    const float* bg1  = (const float*)d_in[7];
    const float* adj2 = (const float*)d_in[8];
    const float* Wg2  = (const float*)d_in[9];
    const float* bg2  = (const float*)d_in[10];
    const float* Wc   = (const float*)d_in[11];
    const float* bc   = (const float*)d_in[12];
    float* out = (float*)d_out;

    const int M = in_sizes[0] / DM;   // 65536 tokens

    float *h_buf = nullptr, *nodes_buf = nullptr;
    cudaGetSymbolAddress((void**)&h_buf, g_h);
    cudaGetSymbolAddress((void**)&nodes_buf, g_nodes);

    // h = gelu(x @ W1 + b1)
    gemm_bias_kernel<true><<<dim3(HIDN / 64, M / 64), 256>>>(
        x, W1, b1, h_buf, M, HIDN, DM);

    // nodes = h @ W2 + b2
    gemm_bias_kernel<false><<<dim3((NODE_TOT + 63) / 64, M / 64), 256>>>(
        h_buf, W2, b2, nodes_buf, M, NODE_TOT, HIDN);

    // GAT1 -> GAT2 -> coord
    gat_kernel<<<2048, 256>>>(nodes_buf, adj1, Wg1, bg1, adj2, Wg2, bg2,
                              Wc, bc, out, M);
}

// round 5
// speedup vs baseline: 1.9307x; 1.9307x over previous
#include <cuda_runtime.h>
#include <math.h>
#include <stdint.h>

#define NTOK   65536
#define DM     128
#define HIDN   256
#define NN     17
#define NF     32
#define NODE_TOT 544
#define CATN   1088           // [nodes | z1]
#define OUTW   34

// Scratch (allocation-free: __device__ globals)
__device__ float g_h[(size_t)NTOK * HIDN];        // 64 MB
__device__ float g_big[(size_t)NTOK * CATN];      // 285 MB: [nodes | z1]
__device__ float g_bt1[HIDN * DM];                // W1^T [256][128]
__device__ float g_bt2[CATN * HIDN];              // [W2^T ; Wfold^T] [1088][256]
__device__ float g_bcat[CATN];                    // [b2 ; bfold]

__device__ __forceinline__ float gelu_erf(float v) {
    return 0.5f * v * (1.0f + erff(v * 0.7071067811865476f));
}
__device__ __forceinline__ uint32_t f2tf32(float x) {
    uint32_t u;
    asm("cvt.rna.tf32.f32 %0, %1;" : "=r"(u) : "f"(x));
    return u;
}
__device__ __forceinline__ void mma_tf32(float* d, const uint32_t* a, const uint32_t* b) {
    asm volatile(
        "mma.sync.aligned.m16n8k8.row.col.f32.tf32.tf32.f32 "
        "{%0,%1,%2,%3}, {%4,%5,%6,%7}, {%8,%9}, {%0,%1,%2,%3};"
        : "+f"(d[0]), "+f"(d[1]), "+f"(d[2]), "+f"(d[3])
        : "r"(a[0]), "r"(a[1]), "r"(a[2]), "r"(a[3]), "r"(b[0]), "r"(b[1]));
}

// ---------------------------------------------------------------------------
// Prep 1: transposes + bias copy.
//   g_bt1[n][k] = W1[k][n];  g_bt2[n][k] = W2[k][n] (n<544);  g_bcat[0:544]=b2
// ---------------------------------------------------------------------------
__global__ void transpose_prep(const float* __restrict__ W1,
                               const float* __restrict__ W2,
                               const float* __restrict__ b2) {
    int i = blockIdx.x * blockDim.x + threadIdx.x;
    const int S1 = HIDN * DM;          // 32768
    const int S2 = NODE_TOT * HIDN;    // 139264
    if (i < S1) {
        int n = i / DM, k = i % DM;
        g_bt1[i] = W1[k * HIDN + n];
    } else if (i < S1 + S2) {
        int t = i - S1;
        int n = t / HIDN, k = t % HIDN;
        g_bt2[t] = W2[k * NODE_TOT + n];
    } else if (i < S1 + S2 + NODE_TOT) {
        int n = i - S1 - S2;
        g_bcat[n] = b2[n];
    }
}

// ---------------------------------------------------------------------------
// Prep 2: fold GAT1 into GEMM2.
//   adj1s = softmax(adj1)
//   Wfold[k,(i,f)] = sum_j adj1s[i][j] * sum_g W2[k,(j,g)] * Wg1[g][f]
//   bfold[(i,f)]   = sum_j adj1s[i][j] * sum_g b2[(j,g)]  * Wg1[g][f] + bg1[f]
// One block per k (256 blocks), 544 threads = one output (i,f) each.
// Writes transposed: g_bt2[(544+(i,f))][k].
// ---------------------------------------------------------------------------
__global__ __launch_bounds__(NODE_TOT) void fold_kernel(
    const float* __restrict__ W2, const float* __restrict__ b2,
    const float* __restrict__ Wg1, const float* __restrict__ bg1,
    const float* __restrict__ adj1)
{
    __shared__ float adjs[NN][NN];
    __shared__ float wg[NF][NF];        // wg[g][f]
    __shared__ float w2row[NODE_TOT];

    const int tid = threadIdx.x;
    const int k = blockIdx.x;

    if (tid < NN) {
        float v[NN];
        float mx = -1e30f;
#pragma unroll
        for (int j = 0; j < NN; j++) { v[j] = adj1[tid * NN + j]; mx = fmaxf(mx, v[j]); }
        float s = 0.0f;
#pragma unroll
        for (int j = 0; j < NN; j++) { v[j] = expf(v[j] - mx); s += v[j]; }
        const float inv = 1.0f / s;
#pragma unroll
        for (int j = 0; j < NN; j++) adjs[tid][j] = v[j] * inv;
    }
    for (int idx = tid; idx < NF * NF; idx += NODE_TOT)
        wg[idx / NF][idx % NF] = Wg1[idx];
    w2row[tid] = W2[k * NODE_TOT + tid];
    __syncthreads();

    const int i = tid >> 5, f = tid & 31;
    float acc = 0.0f;
#pragma unroll 1
    for (int j = 0; j < NN; j++) {
        float s = 0.0f;
#pragma unroll
        for (int g = 0; g < NF; g++) s = fmaf(w2row[j * NF + g], wg[g][f], s);
        acc = fmaf(adjs[i][j], s, acc);
    }
    g_bt2[(size_t)(NODE_TOT + tid) * HIDN + k] = acc;

    if (k == 0) {
        float accb = 0.0f;
#pragma unroll 1
        for (int j = 0; j < NN; j++) {
            float s = 0.0f;
#pragma unroll
            for (int g = 0; g < NF; g++) s = fmaf(b2[j * NF + g], wg[g][f], s);
            accb = fmaf(adjs[i][j], s, accb);
        }
        g_bcat[NODE_TOT + tid] = accb + bg1[f];
    }
}

// ---------------------------------------------------------------------------
// tf32 mma.sync GEMM:  C[M,Nfull] = act(A[M,K] @ Bt[Nfull,K]^T + bias)
// BM=128, BN=128, BK=32. 8 warps as 2(m) x 4(n); warp tile 64x32 via
// 4x4 grid of m16n8k8. Pad-36 smem rows -> conflict-free fragment LDS.
// ---------------------------------------------------------------------------
__global__ __launch_bounds__(256) void gemm_mma(
    const float* __restrict__ A, const float* __restrict__ Bt,
    const float* __restrict__ bias, float* __restrict__ C,
    int K, int Nfull, int do_gelu)
{
    __shared__ float As[128][36];
    __shared__ float Bs[128][36];

    const int tid  = threadIdx.x;
    const int lane = tid & 31;
    const int wid  = tid >> 5;
    const int wm   = wid >> 2;        // 0..1 -> 64-row slab
    const int wn   = wid & 3;         // 0..3 -> 32-col slab
    const int group = lane >> 2;      // 0..7
    const int tg    = lane & 3;       // 0..3

    const int m0 = blockIdx.y * 128;
    const int n0 = blockIdx.x * 128;
    const int NC = min(128, Nfull - n0);

    float acc[4][4][4];
#pragma unroll
    for (int mt = 0; mt < 4; mt++)
#pragma unroll
        for (int nt = 0; nt < 4; nt++)
#pragma unroll
            for (int r = 0; r < 4; r++) acc[mt][nt][r] = 0.0f;

    for (int kb = 0; kb < K; kb += 32) {
        // fill A tile: 128x32 -> 1024 float4 slots
#pragma unroll
        for (int it = 0; it < 4; it++) {
            int idx = tid + it * 256;
            int row = idx >> 3, q = idx & 7;
            const float4 v = *reinterpret_cast<const float4*>(
                A + (size_t)(m0 + row) * K + kb + q * 4);
            uint4 u = make_uint4(f2tf32(v.x), f2tf32(v.y), f2tf32(v.z), f2tf32(v.w));
            *reinterpret_cast<uint4*>(&As[row][q * 4]) = u;
        }
        // fill B tile: NC x 32 (zero-pad rows >= NC)
#pragma unroll
        for (int it = 0; it < 4; it++) {
            int idx = tid + it * 256;
            int row = idx >> 3, q = idx & 7;
            float4 v = make_float4(0.f, 0.f, 0.f, 0.f);
            if (row < NC)
                v = *reinterpret_cast<const float4*>(
                    Bt + (size_t)(n0 + row) * K + kb + q * 4);
            uint4 u = make_uint4(f2tf32(v.x), f2tf32(v.y), f2tf32(v.z), f2tf32(v.w));
            *reinterpret_cast<uint4*>(&Bs[row][q * 4]) = u;
        }
        __syncthreads();

#pragma unroll
        for (int ks = 0; ks < 4; ks++) {
            const int kk = ks * 8;
            uint32_t a[4][4], b[4][2];
#pragma unroll
            for (int mt = 0; mt < 4; mt++) {
                const int r = wm * 64 + mt * 16 + group;
                a[mt][0] = __float_as_uint(As[r][kk + tg]);
                a[mt][1] = __float_as_uint(As[r + 8][kk + tg]);
                a[mt][2] = __float_as_uint(As[r][kk + tg + 4]);
                a[mt][3] = __float_as_uint(As[r + 8][kk + tg + 4]);
            }
#pragma unroll
            for (int nt = 0; nt < 4; nt++) {
                const int c = wn * 32 + nt * 8 + group;
                b[nt][0] = __float_as_uint(Bs[c][kk + tg]);
                b[nt][1] = __float_as_uint(Bs[c][kk + tg + 4]);
            }
#pragma unroll
            for (int mt = 0; mt < 4; mt++)
#pragma unroll
                for (int nt = 0; nt < 4; nt++)
                    mma_tf32(acc[mt][nt], a[mt], b[nt]);
        }
        __syncthreads();
    }

    // epilogue
#pragma unroll
    for (int mt = 0; mt < 4; mt++) {
        const int row = m0 + wm * 64 + mt * 16 + group;
#pragma unroll
        for (int nt = 0; nt < 4; nt++) {
            const int col = n0 + wn * 32 + nt * 8 + tg * 2;
            if (col < Nfull) {
                const float bz0 = bias[col], bz1 = bias[col + 1];
                float v0 = acc[mt][nt][0] + bz0;
                float v1 = acc[mt][nt][1] + bz1;
                float v2 = acc[mt][nt][2] + bz0;
                float v3 = acc[mt][nt][3] + bz1;
                if (do_gelu) {
                    v0 = gelu_erf(v0); v1 = gelu_erf(v1);
                    v2 = gelu_erf(v2); v3 = gelu_erf(v3);
                }
                *reinterpret_cast<float2*>(&C[(size_t)row * Nfull + col]) =
                    make_float2(v0, v1);
                *reinterpret_cast<float2*>(&C[(size_t)(row + 8) * Nfull + col]) =
                    make_float2(v2, v3);
            }
        }
    }
}

// ---------------------------------------------------------------------------
// GAT stage: layer1 collapsed to elementwise (z1 precomputed by GEMM2),
// then GAT2 + coord. One warp per token, lane = feature.
// ---------------------------------------------------------------------------
__global__ __launch_bounds__(256) void gat2_kernel(
    const float* __restrict__ big,
    const float* __restrict__ adj2, const float* __restrict__ Wg2, const float* __restrict__ bg2,
    const float* __restrict__ Wc,  const float* __restrict__ bc,
    float* __restrict__ out, int ntok)
{
    __shared__ float a2s[NN][NN];

    const int tid = threadIdx.x;

    if (tid < NN) {
        float v[NN];
        float mx = -1e30f;
#pragma unroll
        for (int j = 0; j < NN; j++) { v[j] = adj2[tid * NN + j]; mx = fmaxf(mx, v[j]); }
        float s = 0.0f;
#pragma unroll
        for (int j = 0; j < NN; j++) { v[j] = expf(v[j] - mx); s += v[j]; }
        const float inv = 1.0f / s;
#pragma unroll
        for (int j = 0; j < NN; j++) a2s[tid][j] = v[j] * inv;
    }
    __syncthreads();

    const int lane = tid & 31;
    const int warp = tid >> 5;

    float wg2[NF];
#pragma unroll
    for (int g = 0; g < NF; g++) wg2[g] = Wg2[g * NF + lane];
    const float bg2v = bg2[lane];
    const float wc0 = Wc[lane * 2 + 0];
    const float wc1 = Wc[lane * 2 + 1];
    const float bc0 = bc[0], bc1 = bc[1];

    const int gw = blockIdx.x * (blockDim.x >> 5) + warp;
    const int nwarps = gridDim.x * (blockDim.x >> 5);

    for (int t = gw; t < ntok; t += nwarps) {
        const float* bp = big + (size_t)t * CATN;
        float n[NN];
#pragma unroll
        for (int j = 0; j < NN; j++) {
            const float nd = bp[j * NF + lane];             // nodes
            const float z1 = bp[NODE_TOT + j * NF + lane];  // pre-GELU GAT1
            n[j] = gelu_erf(z1) + nd;
        }

        // ---- GAT layer 2 ----
        float mx2[NN];
#pragma unroll
        for (int i = 0; i < NN; i++) {
            float m = 0.0f;
#pragma unroll
            for (int j = 0; j < NN; j++) m = fmaf(a2s[i][j], n[j], m);
            mx2[i] = m;
        }
#pragma unroll
        for (int i = 0; i < NN; i++) {
            float acc = bg2v;
#pragma unroll
            for (int g = 0; g < NF; g++)
                acc = fmaf(__shfl_sync(0xffffffffu, mx2[i], g), wg2[g], acc);
            n[i] = gelu_erf(acc) + n[i];
        }

        // ---- coord projection ----
#pragma unroll
        for (int i = 0; i < NN; i++) {
            float v0 = n[i] * wc0;
            float v1 = n[i] * wc1;
#pragma unroll
            for (int off = 16; off > 0; off >>= 1) {
                v0 += __shfl_xor_sync(0xffffffffu, v0, off);
                v1 += __shfl_xor_sync(0xffffffffu, v1, off);
            }
            if (lane == 0) {
                out[(size_t)t * OUTW + i * 2 + 0] = v0 + bc0;
                out[(size_t)t * OUTW + i * 2 + 1] = v1 + bc1;
            }
        }
    }
}

// ---------------------------------------------------------------------------
extern "C" void kernel_launch(void* const* d_in, const int* in_sizes, int n_in,
                              void* d_out, int out_size)
{
    const float* x    = (const float*)d_in[0];
    const float* W1   = (const float*)d_in[1];
    const float* b1   = (const float*)d_in[2];
    const float* W2   = (const float*)d_in[3];
    const float* b2   = (const float*)d_in[4];
    const float* adj1 = (const float*)d_in[5];
    const float* Wg1  = (const float*)d_in[6];
    const float* bg1  = (const float*)d_in[7];
    const float* adj2 = (const float*)d_in[8];
    const float* Wg2  = (const float*)d_in[9];
    const float* bg2  = (const float*)d_in[10];
    const float* Wc   = (const float*)d_in[11];
    const float* bc   = (const float*)d_in[12];
    float* out = (float*)d_out;

    const int M = in_sizes[0] / DM;   // 65536 tokens

    float *h_buf = nullptr, *big_buf = nullptr, *bt1 = nullptr, *bt2 = nullptr, *bcat = nullptr;
    cudaGetSymbolAddress((void**)&h_buf, g_h);
    cudaGetSymbolAddress((void**)&big_buf, g_big);
    cudaGetSymbolAddress((void**)&bt1, g_bt1);
    cudaGetSymbolAddress((void**)&bt2, g_bt2);
    cudaGetSymbolAddress((void**)&bcat, g_bcat);

    // Prep: transposes + GAT1 fold
    const int TT = HIDN * DM + NODE_TOT * HIDN + NODE_TOT;
    transpose_prep<<<(TT + 255) / 256, 256>>>(W1, W2, b2);
    fold_kernel<<<HIDN, NODE_TOT>>>(W2, b2, Wg1, bg1, adj1);

    // h = gelu(x @ W1 + b1)            [tf32 mma.sync]
    gemm_mma<<<dim3(HIDN / 128, M / 128), 256>>>(x, bt1, b1, h_buf, DM, HIDN, 1);

    // [nodes | z1] = h @ [W2 | Wfold] + [b2 | bfold]
    gemm_mma<<<dim3((CATN + 127) / 128, M / 128), 256>>>(h_buf, bt2, bcat, big_buf,
                                                         HIDN, CATN, 0);

    // elementwise GAT1 finish + GAT2 + coord
    gat2_kernel<<<2048, 256>>>(big_buf, adj2, Wg2, bg2, Wc, bc, out, M);
}